// round 7
// baseline (speedup 1.0000x reference)
#include <cuda_runtime.h>
#include <math.h>

#define BB 64
#define NN 512
#define DD 128
#define MM 128
#define NEG_INF -1e9f

// Scratch (device globals)
__device__ float g_M[DD * DD];        // M[e][d] = Wk row e . Wq row d
__device__ float g_part[BB * 8 * 128];// per-(batch,chunk) partial masked sums
__device__ float g_G[BB * DD];        // per-batch G vector
__device__ float g_C[BB];             // per-batch scalar
__device__ float g_agg[BB * NN];      // pre-normalize agg
__device__ int   g_actc[BB * NN];     // per-chunk compacted indices
__device__ int   g_ccnt[BB * 8];      // per-chunk active counts
__device__ int   g_act[BB * NN];      // dense per-batch active list
__device__ int   g_cnt[BB];           // per-batch active count

__device__ __forceinline__ float warp_sum(float v) {
#pragma unroll
    for (int o = 16; o; o >>= 1) v += __shfl_xor_sync(0xffffffffu, v, o);
    return v;
}
__device__ __forceinline__ float warp_max(float v) {
#pragma unroll
    for (int o = 16; o; o >>= 1) v = fmaxf(v, __shfl_xor_sync(0xffffffffu, v, o));
    return v;
}
__device__ __forceinline__ float dot4(float4 a, float4 b) {
    return a.x * b.x + a.y * b.y + a.z * b.z + a.w * b.w;
}

// ---------------------------------------------------------------------------
// K1: full-chip cold scan of A.
//   blocks 0..511  : (b, chunk) partial masked sum of 64 rows + per-chunk
//                    ballot compaction + zero agg slice.
//   blocks 512..527: M[e][d] (8 warps -> 8 e-rows per block).
// ---------------------------------------------------------------------------
__global__ __launch_bounds__(256) void scan_kernel(
    const float* __restrict__ A, const float* __restrict__ mask,
    const float* __restrict__ Wq, const float* __restrict__ Wk)
{
    const int warp = threadIdx.x >> 5, lane = threadIdx.x & 31, tid = threadIdx.x;
    const float4* Wq4 = (const float4*)Wq;
    const float4* Wk4 = (const float4*)Wk;

    if (blockIdx.x >= BB * 8) {
        const int e = (blockIdx.x - BB * 8) * 8 + warp;   // 16 blocks * 8 = 128
        float4 wk = Wk4[e * 32 + lane];
        for (int d = 0; d < DD; d += 2) {
            float p0 = dot4(wk, Wq4[d * 32 + lane]);
            float p1 = dot4(wk, Wq4[(d + 1) * 32 + lane]);
            p0 = warp_sum(p0);
            p1 = warp_sum(p1);
            if (lane == 0) { g_M[e * DD + d] = p0; g_M[e * DD + d + 1] = p1; }
        }
        return;
    }

    const int b = blockIdx.x >> 3;
    const int c = blockIdx.x & 7;
    const int r0 = c * 64;
    const size_t base = (size_t)b * NN;
    const float4* A4 = (const float4*)A;

    __shared__ float sW[8][128];

    // Branchless partial masked sum over 64 rows (8 rows per warp).
    float4 acc = make_float4(0.f, 0.f, 0.f, 0.f);
#pragma unroll
    for (int i = r0 + warp; i < r0 + 64; i += 8) {
        float m = mask[base + i];
        float4 a = A4[(base + i) * 32 + lane];
        acc.x = fmaf(m, a.x, acc.x);
        acc.y = fmaf(m, a.y, acc.y);
        acc.z = fmaf(m, a.z, acc.z);
        acc.w = fmaf(m, a.w, acc.w);
    }
    ((float4*)sW[warp])[lane] = acc;

    // Zero agg slice.
    if (tid < 64) g_agg[base + r0 + tid] = 0.f;

    // Per-chunk ballot compaction (warp 0): rows r0..r0+63.
    if (warp == 0) {
        float m0 = mask[base + r0 + lane];
        float m1 = mask[base + r0 + 32 + lane];
        unsigned b0 = __ballot_sync(0xffffffffu, m0 > 0.f);
        unsigned b1 = __ballot_sync(0xffffffffu, m1 > 0.f);
        int c0 = __popc(b0);
        int pre0 = __popc(b0 & ((1u << lane) - 1u));
        int pre1 = __popc(b1 & ((1u << lane) - 1u));
        int* dst = g_actc + base + r0;
        if (m0 > 0.f) dst[pre0] = r0 + lane;
        if (m1 > 0.f) dst[c0 + pre1] = r0 + 32 + lane;
        if (lane == 0) g_ccnt[b * 8 + c] = c0 + __popc(b1);
    }
    __syncthreads();

    if (tid < 128) {
        float s = 0.f;
#pragma unroll
        for (int w = 0; w < 8; w++) s += sW[w][tid];
        g_part[((size_t)b * 8 + c) * 128 + tid] = s;
    }
}

// ---------------------------------------------------------------------------
// K2: per-batch stats (grid BB, 128 threads):
//   asum from partials, dense active list from per-chunk lists, qs, C, G.
// ---------------------------------------------------------------------------
__global__ __launch_bounds__(128) void stats_kernel(
    const float* __restrict__ Wq, const float* __restrict__ Wk,
    const float* __restrict__ bq, const float* __restrict__ bk)
{
    const int b = blockIdx.x;
    const int warp = threadIdx.x >> 5, lane = threadIdx.x & 31, tid = threadIdx.x;
    const size_t base = (size_t)b * NN;
    const float4* Wq4 = (const float4*)Wq;
    const float4* Wk4 = (const float4*)Wk;

    __shared__ float asum[128];
    __shared__ float qs[128];

    // Prefix offsets over 8 chunk counts (each thread redundantly).
    int cc[8], off[8], tot = 0;
#pragma unroll
    for (int c = 0; c < 8; c++) {
        cc[c] = g_ccnt[b * 8 + c];
        off[c] = tot;
        tot += cc[c];
    }
    if (tid == 0) g_cnt[b] = tot;

    // Stitch dense active list.
#pragma unroll
    for (int c = 0; c < 8; c++)
        for (int j = tid; j < cc[c]; j += 128)
            g_act[base + off[c] + j] = g_actc[base + c * 64 + j];

    // asum = sum of 8 partials.
    {
        float s = 0.f;
#pragma unroll
        for (int c = 0; c < 8; c++) s += g_part[((size_t)b * 8 + c) * 128 + tid];
        asum[tid] = s;
    }
    __syncthreads();

    const float cnt = (float)tot;

    // qs[m] = sum_d asum[d]*Wq[d,m] + cnt*bq[m]
    {
        float q = cnt * bq[tid];
#pragma unroll 8
        for (int d = 0; d < DD; d++) q = fmaf(asum[d], Wq[d * MM + tid], q);
        qs[tid] = q;
    }
    __syncthreads();

    // C = sum_m bk[m]*(qs[m]-bq[m])
    if (warp == 0) {
        float c = 0.f;
        for (int m = lane; m < MM; m += 32) c = fmaf(bk[m], qs[m] - bq[m], c);
        c = warp_sum(c);
        if (lane == 0) g_C[b] = c;
    }

    // G[d] = Wk row d . qs - Wq row d . bk
    {
        float4 qs4 = ((const float4*)qs)[lane];
        float4 bk4 = ((const float4*)bk)[lane];
#pragma unroll
        for (int d = warp; d < DD; d += 4) {
            float p = dot4(Wk4[d * 32 + lane], qs4) - dot4(Wq4[d * 32 + lane], bk4);
            p = warp_sum(p);
            if (lane == 0) g_G[b * DD + d] = p;
        }
    }
}

// ---------------------------------------------------------------------------
// K3: quadratic form, smem-staged. agg_i = A_i.G - A_i M A_i^T + C
// ---------------------------------------------------------------------------
__global__ __launch_bounds__(256) void quad_kernel(const float* __restrict__ A)
{
    const int b = blockIdx.x >> 3;
    const int j0 = (blockIdx.x & 7) * 64;
    const int nact = g_cnt[b];
    if (j0 >= nact) return;

    extern __shared__ float4 smem4[];
    float4* sM4 = smem4;                 // 64KB
    float4* sA4 = smem4 + 4096;          // 32KB
    int* sAct = (int*)(smem4 + 4096 + 2048);

    const int warp = threadIdx.x >> 5, lane = threadIdx.x & 31, tid = threadIdx.x;
    const size_t base = (size_t)b * NN;
    const float4* A4 = (const float4*)A;
    const float4* gM4 = (const float4*)g_M;

    if (tid < 64) {
        int j = j0 + tid;
        sAct[tid] = (j < nact) ? g_act[base + j] : -1;
    }
#pragma unroll 4
    for (int idx = tid; idx < 4096; idx += 256) sM4[idx] = gM4[idx];
    __syncthreads();
#pragma unroll 2
    for (int idx = tid; idx < 2048; idx += 256) {
        int r = idx >> 5, cth = idx & 31;
        int row = sAct[r];
        sA4[idx] = (row >= 0) ? A4[(base + row) * 32 + cth]
                              : make_float4(0.f, 0.f, 0.f, 0.f);
    }
    __syncthreads();

    const int rbase = warp * 8;
    float4 y[8];
#pragma unroll
    for (int r = 0; r < 8; r++) y[r] = make_float4(0.f, 0.f, 0.f, 0.f);

    for (int e4 = 0; e4 < 32; e4++) {
        float4 av[8];
#pragma unroll
        for (int r = 0; r < 8; r++) av[r] = sA4[(rbase + r) * 32 + e4];
#pragma unroll
        for (int s = 0; s < 4; s++) {
            float4 mc = sM4[(e4 * 4 + s) * 32 + lane];
#pragma unroll
            for (int r = 0; r < 8; r++) {
                float a = (s == 0) ? av[r].x : (s == 1) ? av[r].y
                        : (s == 2) ? av[r].z : av[r].w;
                y[r].x = fmaf(a, mc.x, y[r].x);
                y[r].y = fmaf(a, mc.y, y[r].y);
                y[r].z = fmaf(a, mc.z, y[r].z);
                y[r].w = fmaf(a, mc.w, y[r].w);
            }
        }
    }

    float4 G = ((const float4*)(g_G + b * DD))[lane];
    const float C = g_C[b];
#pragma unroll
    for (int r = 0; r < 8; r++) {
        int row = sAct[rbase + r];
        float4 a = sA4[(rbase + r) * 32 + lane];
        float p = a.x * (G.x - y[r].x) + a.y * (G.y - y[r].y)
                + a.z * (G.z - y[r].z) + a.w * (G.w - y[r].w);
        p = warp_sum(p);
        if (lane == 0 && row >= 0) g_agg[base + row] = p + C;
    }
}

// ---------------------------------------------------------------------------
// K4: normalize -> masked softmax -> attn out; context = wsum@Wk + bk
// ---------------------------------------------------------------------------
__global__ __launch_bounds__(1024) void softmax_ctx_kernel(
    const float* __restrict__ A, const float* __restrict__ mask,
    const float* __restrict__ Wk, const float* __restrict__ bk,
    float* __restrict__ out)
{
    const int b = blockIdx.x;
    const int warp = threadIdx.x >> 5, lane = threadIdx.x & 31, tid = threadIdx.x;
    const size_t base = (size_t)b * NN;
    const float4* A4 = (const float4*)A;

    __shared__ float sc[NN];
    __shared__ float sRed[32];
    __shared__ float sW[32][128];
    __shared__ float wsum[128];

    float ss = 0.f;
    for (int i = tid; i < NN; i += 1024) {
        float v = g_agg[base + i];
        sc[i] = v;
        ss = fmaf(v, v, ss);
    }
    ss = warp_sum(ss);
    if (lane == 0) sRed[warp] = ss;
    __syncthreads();
    float tot = 0.f;
#pragma unroll
    for (int w = 0; w < 32; w++) tot += sRed[w];
    float inv = rsqrtf(tot);

    float mx = -INFINITY;
    for (int i = tid; i < NN; i += 1024) {
        float m = mask[base + i];
        float s = (m > 0.f) ? sc[i] * inv : NEG_INF;
        sc[i] = s;
        mx = fmaxf(mx, s);
    }
    mx = warp_max(mx);
    __syncthreads();
    if (lane == 0) sRed[warp] = mx;
    __syncthreads();
    float M = -INFINITY;
#pragma unroll
    for (int w = 0; w < 32; w++) M = fmaxf(M, sRed[w]);

    float es = 0.f;
    for (int i = tid; i < NN; i += 1024) {
        float e = __expf(sc[i] - M);
        sc[i] = e;
        es += e;
    }
    es = warp_sum(es);
    __syncthreads();
    if (lane == 0) sRed[warp] = es;
    __syncthreads();
    float S = 0.f;
#pragma unroll
    for (int w = 0; w < 32; w++) S += sRed[w];
    float invS = 1.0f / S;

    for (int i = tid; i < NN; i += 1024) {
        float at = sc[i] * invS;
        sc[i] = at;
        out[base + i] = at;
    }
    __syncthreads();

    float4 wacc = make_float4(0.f, 0.f, 0.f, 0.f);
#pragma unroll
    for (int i = warp; i < NN; i += 32) {
        float at = sc[i];
        float4 a = A4[(base + i) * 32 + lane];
        wacc.x = fmaf(at, a.x, wacc.x);
        wacc.y = fmaf(at, a.y, wacc.y);
        wacc.z = fmaf(at, a.z, wacc.z);
        wacc.w = fmaf(at, a.w, wacc.w);
    }
    ((float4*)sW[warp])[lane] = wacc;
    __syncthreads();
    if (tid < 128) {
        float s = 0.f;
#pragma unroll
        for (int w = 0; w < 32; w++) s += sW[w][tid];
        wsum[tid] = s;
    }
    __syncthreads();

    if (tid < 128) {
        float c = bk[tid];
#pragma unroll 8
        for (int d = 0; d < DD; d++) c = fmaf(wsum[d], Wk[d * MM + tid], c);
        out[(size_t)BB * NN + (size_t)b * MM + tid] = c;
    }
}

extern "C" void kernel_launch(void* const* d_in, const int* in_sizes, int n_in,
                              void* d_out, int out_size)
{
    const float* A    = (const float*)d_in[0];
    const float* mask = (const float*)d_in[1];
    const float* Wq   = (const float*)d_in[2];
    const float* bq   = (const float*)d_in[3];
    const float* Wk   = (const float*)d_in[4];
    const float* bk   = (const float*)d_in[5];
    float* out = (float*)d_out;

    const int quad_smem = 4096 * 16 + 2048 * 16 + 256;   // 98560 B
    cudaFuncSetAttribute(quad_kernel,
                         cudaFuncAttributeMaxDynamicSharedMemorySize, quad_smem);

    scan_kernel<<<BB * 8 + 16, 256>>>(A, mask, Wq, Wk);
    stats_kernel<<<BB, 128>>>(Wq, Wk, bq, bk);
    quad_kernel<<<BB * 8, 256, quad_smem>>>(A);
    softmax_ctx_kernel<<<BB, 1024>>>(A, mask, Wk, bk, out);
}